// round 8
// baseline (speedup 1.0000x reference)
#include <cuda_runtime.h>
#include <cuda_fp16.h>
#include <cstdint>
#include <math.h>

#define NT 16384
#define HH 2048
#define NE 64
#define NB 4
#define NS 4096
#define TM 128          // tokens per CTA
#define KT 64           // K elems per tile
#define NTILES (HH/KT)  // 32
#define THREADS 256
#define SMEM_BYTES 49408
#define TAU 5e-3f
#define MAXFIX 16384

// persistent scratch (allocation-free rule: __device__ globals)
__device__ float    g_ssum[NB * NE];
__device__ int      g_cnt[NB * NE];
__device__ uint32_t g_wh[NE * HH / 2];   // fp16x2-packed W
__device__ int      g_nfix;
__device__ int      g_fix[MAXFIX];

// ---------------- helpers ----------------
__device__ __forceinline__ uint32_t smem_u32(const void* p) {
    uint32_t a;
    asm("{ .reg .u64 t; cvta.to.shared.u64 t, %1; cvt.u32.u64 %0, t; }" : "=r"(a) : "l"(p));
    return a;
}
// pack two fp32 -> fp16x2 (lo arg -> bits[15:0], hi arg -> bits[31:16])
__device__ __forceinline__ uint32_t pack2h(float lo, float hi) {
    uint32_t r;
    asm("cvt.rn.f16x2.f32 %0, %1, %2;" : "=r"(r) : "f"(hi), "f"(lo));
    return r;
}
__device__ __forceinline__ void ldsm4(uint32_t* r, uint32_t addr) {
    asm volatile("ldmatrix.sync.aligned.m8n8.x4.shared.b16 {%0,%1,%2,%3}, [%4];"
                 : "=r"(r[0]), "=r"(r[1]), "=r"(r[2]), "=r"(r[3]) : "r"(addr));
}
__device__ __forceinline__ void mma16816(float* d, const uint32_t* a, const uint32_t* b) {
    asm volatile("mma.sync.aligned.m16n8k16.row.col.f32.f16.f16.f32 "
                 "{%0,%1,%2,%3}, {%4,%5,%6,%7}, {%8,%9}, {%0,%1,%2,%3};"
                 : "+f"(d[0]), "+f"(d[1]), "+f"(d[2]), "+f"(d[3])
                 : "r"(a[0]), "r"(a[1]), "r"(a[2]), "r"(a[3]), "r"(b[0]), "r"(b[1]));
}

// ---------------- W convert kernel (+ fixup counter reset) ----------------
__global__ __launch_bounds__(256) void k_wconv(const float* __restrict__ W) {
    if (blockIdx.x == 0 && threadIdx.x == 0) g_nfix = 0;
    int i = (blockIdx.x * 256 + threadIdx.x) * 4;
    float4 v = *(const float4*)(W + i);
    ((uint2*)g_wh)[i >> 2] = make_uint2(pack2h(v.x, v.y), pack2h(v.z, v.w));
}

// ---------------- main gate kernel (single fp16 HMMA product) ----------------
__global__ __launch_bounds__(THREADS, 1)
void k_gate(const float* __restrict__ X, float* __restrict__ out, int wbase) {
    extern __shared__ char smem[];
    const int tid  = threadIdx.x;
    const int wid  = tid >> 5;
    const int lane = tid & 31;
    const uint32_t sb = smem_u32(smem);
    const int tokBase = blockIdx.x * TM;

    int* scnt = (int*)(smem + 49152);
    if (tid < NE) scnt[tid] = 0;

    // smem: A(s) = sb + s*16384 (128 rows x 128B); B(s) = sb + 32768 + s*8192 (64 rows x 128B)
    const uint32_t HA = sb;
    const uint32_t HB = sb + 32768u;

    // ---- gmem addressing ----
    const int xr = tid >> 4;
    const float* xp = X + (size_t)(tokBase + xr) * HH + (tid & 15) * 4;
    const int wr = tid >> 3;
    const int wc = tid & 7;
    const int wbase4 = wr * 256 + wc;   // uint4 idx into g_wh rows

    // ---- STS swizzled offsets ----
    uint32_t xoff[8], woff[2];
#pragma unroll
    for (int p = 0; p < 8; p++) {
        uint32_t off = (uint32_t)(xr + 16 * p) * 128u + (uint32_t)(tid & 15) * 8u;
        xoff[p] = off ^ ((off >> 3) & 0x70);
    }
#pragma unroll
    for (int q = 0; q < 2; q++) {
        uint32_t off = (uint32_t)(wr + 32 * q) * 128u + (uint32_t)wc * 16u;
        woff[q] = off ^ ((off >> 3) & 0x70);
    }

    // ---- LDSM addressing ----
    const int wm = wid & 3;
    const int wn = wid >> 2;
    const uint32_t xorK  = (uint32_t)(lane & 7);
    const uint32_t kselA = (uint32_t)(lane >> 4);
    const uint32_t kselB = (uint32_t)((lane >> 3) & 1);
    uint32_t rowA[2], rowB[2];
#pragma unroll
    for (int mt = 0; mt < 2; mt++)
        rowA[mt] = (uint32_t)(wm * 32 + mt * 16 + (lane & 15)) * 128u;
    {
        int nB = ((lane >> 4) * 8) + (lane & 7);
#pragma unroll
        for (int pr = 0; pr < 2; pr++)
            rowB[pr] = (uint32_t)(wn * 32 + pr * 16 + nB) * 128u;
    }

    float acc[2][4][4];
#pragma unroll
    for (int mt = 0; mt < 2; mt++)
#pragma unroll
        for (int q = 0; q < 4; q++)
#pragma unroll
            for (int e = 0; e < 4; e++) acc[mt][q][e] = 0.0f;

    // ---- prologue: load tile 0 into regs ----
    float4 xv[8];
    uint4 wv[2];
#pragma unroll
    for (int p = 0; p < 8; p++) xv[p] = *(const float4*)(xp + (size_t)p * 16 * HH);
#pragma unroll
    for (int q = 0; q < 2; q++) wv[q] = ((const uint4*)g_wh)[wbase4 + q * 8192];

    for (int t = 0; t < NTILES; t++) {
        const int s = t & 1;
        const uint32_t A = HA + (uint32_t)s * 16384u;
        const uint32_t B = HB + (uint32_t)s * 8192u;

        // convert + STS current tile
#pragma unroll
        for (int p = 0; p < 8; p++) {
            uint32_t h01 = pack2h(xv[p].x, xv[p].y);
            uint32_t h23 = pack2h(xv[p].z, xv[p].w);
            asm volatile("st.shared.v2.u32 [%0], {%1,%2};" :: "r"(A + xoff[p]), "r"(h01), "r"(h23));
        }
#pragma unroll
        for (int q = 0; q < 2; q++)
            asm volatile("st.shared.v4.b32 [%0], {%1,%2,%3,%4};"
                         :: "r"(B + woff[q]), "r"(wv[q].x), "r"(wv[q].y), "r"(wv[q].z), "r"(wv[q].w));

        // prefetch next tile (overlaps sync + MMA)
        if (t + 1 < NTILES) {
            const int tn = t + 1;
#pragma unroll
            for (int p = 0; p < 8; p++)
                xv[p] = *(const float4*)(xp + tn * KT + (size_t)p * 16 * HH);
#pragma unroll
            for (int q = 0; q < 2; q++)
                wv[q] = ((const uint4*)g_wh)[wbase4 + tn * 8 + q * 8192];
        }

        __syncthreads();

        // ---- ldmatrix + mma over buf s ----
#pragma unroll
        for (int ks = 0; ks < 4; ks++) {
            const uint32_t kA = (uint32_t)(2 * ks) + kselA;
            const uint32_t kB = (uint32_t)(2 * ks) + kselB;
            uint32_t bf[8];
#pragma unroll
            for (int pr = 0; pr < 2; pr++)
                ldsm4(&bf[pr * 4], B + rowB[pr] + ((kB ^ xorK) << 4));
            uint32_t af[2][4];
            ldsm4(af[0], A + rowA[0] + ((kA ^ xorK) << 4));
            ldsm4(af[1], A + rowA[1] + ((kA ^ xorK) << 4));
#pragma unroll
            for (int mt = 0; mt < 2; mt++)
#pragma unroll
                for (int q = 0; q < 4; q++)
                    mma16816(acc[mt][q], af[mt], &bf[q * 2]);
        }
    }

    __syncthreads();   // buffers free; reuse as logits

    // ---- accumulators -> logits smem [128][66] ----
    float* Lg = (float*)smem;
    {
        const int g  = lane >> 2;
        const int tg = lane & 3;
#pragma unroll
        for (int mt = 0; mt < 2; mt++)
#pragma unroll
            for (int q = 0; q < 4; q++) {
                int m0 = wm * 32 + mt * 16 + g;
                int c  = wn * 32 + q * 8 + tg * 2;
                Lg[m0 * 66 + c]           = acc[mt][q][0];
                Lg[m0 * 66 + c + 1]       = acc[mt][q][1];
                Lg[(m0 + 8) * 66 + c]     = acc[mt][q][2];
                Lg[(m0 + 8) * 66 + c + 1] = acc[mt][q][3];
            }
    }
    __syncthreads();

    // ---- per-token softmax / top-2 (+ near-tie flagging) ----
    if (tid < TM) {
        float v[64];
#pragma unroll
        for (int e = 0; e < NE; e++) v[e] = Lg[tid * 66 + e];

        float m = -1e30f;
#pragma unroll
        for (int e = 0; e < NE; e++) m = fmaxf(m, v[e]);

        float Z = 0.0f, b1 = -1e30f, b2 = -1e30f, b3 = -1e30f;
        int i1 = 0, i2 = 0;
#pragma unroll
        for (int e = 0; e < NE; e++) {
            float x = v[e];
            float ex = __expf(x - m);
            v[e] = ex;
            Z += ex;
            if (x > b1)      { b3 = b2; b2 = b1; i2 = i1; b1 = x; i1 = e; }
            else if (x > b2) { b3 = b2; b2 = x;  i2 = e; }
            else if (x > b3) { b3 = x; }
        }
        float invZ = 1.0f / Z;
        float s1 = v[i1] * invZ;
        float s2 = v[i2] * invZ;
        float den = s1 + s2 + 1e-20f;

        int gt = tokBase + tid;
        out[gt * 2 + 0] = (float)i1;
        out[gt * 2 + 1] = (float)i2;
        out[wbase + gt * 2 + 0] = s1 / den;
        out[wbase + gt * 2 + 1] = s2 / den;

        if ((b1 - b2 < TAU) || (b2 - b3 < TAU)) {
            int slot = atomicAdd(&g_nfix, 1);
            if (slot < MAXFIX) g_fix[slot] = gt;
        }

        atomicAdd(&scnt[i1], 1);
        atomicAdd(&scnt[i2], 1);

#pragma unroll
        for (int e = 0; e < NE; e++) Lg[tid * 66 + e] = v[e] * invZ;
    }
    __syncthreads();

    if (tid < NE) {
        float ssum = 0.0f;
        for (int r = 0; r < TM; r++) ssum += Lg[r * 66 + tid];
        const int b = tokBase >> 12;
        atomicAdd(&g_ssum[b * NE + tid], ssum);
        int c = scnt[tid];
        if (c) atomicAdd(&g_cnt[b * NE + tid], c);
    }
}

// ---------------- fp32 exact fixup for near-tie tokens ----------------
__global__ __launch_bounds__(256) void k_fixup(const float* __restrict__ X,
                                               const float* __restrict__ W,
                                               float* __restrict__ out, int wbase) {
    __shared__ float part[256];
    __shared__ float lg[64];
    int n = g_nfix;
    if (n > MAXFIX) n = MAXFIX;
    const int tid = threadIdx.x;
    const int e = tid & 63;
    const int j = tid >> 6;

    for (int s = blockIdx.x; s < n; s += gridDim.x) {
        int gt = g_fix[s];
        const float* xr = X + (size_t)gt * HH;
        const float* wr = W + (size_t)e * HH;
        float a0 = 0.f, a1 = 0.f, a2 = 0.f, a3 = 0.f;
        int k0 = j * 512;
#pragma unroll 4
        for (int k = k0; k < k0 + 512; k += 4) {
            a0 = fmaf(xr[k + 0], wr[k + 0], a0);
            a1 = fmaf(xr[k + 1], wr[k + 1], a1);
            a2 = fmaf(xr[k + 2], wr[k + 2], a2);
            a3 = fmaf(xr[k + 3], wr[k + 3], a3);
        }
        part[tid] = (a0 + a1) + (a2 + a3);
        __syncthreads();
        if (tid < 64) lg[e] = (part[e] + part[e + 64]) + (part[e + 128] + part[e + 192]);
        __syncthreads();
        if (tid == 0) {
            float m = -1e30f;
            for (int q = 0; q < 64; q++) m = fmaxf(m, lg[q]);
            float Z = 0.f, b1 = -1e30f, b2 = -1e30f;
            int i1 = 0, i2 = 0;
            for (int q = 0; q < 64; q++) {
                float x = lg[q];
                Z += __expf(x - m);
                if (x > b1)      { b2 = b1; i2 = i1; b1 = x; i1 = q; }
                else if (x > b2) { b2 = x;  i2 = q; }
            }
            float s1 = __expf(b1 - m) / Z;
            float s2 = __expf(b2 - m) / Z;
            float den = s1 + s2 + 1e-20f;

            int o1 = (int)out[gt * 2 + 0];
            int o2 = (int)out[gt * 2 + 1];
            const int b = gt >> 12;
            if (o1 != i1) { atomicAdd(&g_cnt[b * NE + o1], -1); atomicAdd(&g_cnt[b * NE + i1], 1); }
            if (o2 != i2) { atomicAdd(&g_cnt[b * NE + o2], -1); atomicAdd(&g_cnt[b * NE + i2], 1); }

            out[gt * 2 + 0] = (float)i1;
            out[gt * 2 + 1] = (float)i2;
            out[wbase + gt * 2 + 0] = s1 / den;
            out[wbase + gt * 2 + 1] = s2 / den;
        }
        __syncthreads();
    }
}

// ---------------- aux loss + scratch reset ----------------
__global__ void k_aux(float* __restrict__ out, int aux_idx) {
    __shared__ float red[NB * NE];
    int i = threadIdx.x;
    float v = (float)g_cnt[i] * ((float)NE / (float)(NS * 2)) * (g_ssum[i] / (float)NS);
    red[i] = v;
    g_cnt[i] = 0;       // reset for next graph replay
    g_ssum[i] = 0.0f;
    __syncthreads();
    for (int s = 128; s > 0; s >>= 1) {
        if (i < s) red[i] += red[i + s];
        __syncthreads();
    }
    if (i == 0) out[aux_idx] = red[0] / (float)NB * 0.1f;
}

extern "C" void kernel_launch(void* const* d_in, const int* in_sizes, int n_in,
                              void* d_out, int out_size) {
    const float* X = (const float*)d_in[0];   // [4,4096,2048] fp32
    const float* W = (const float*)d_in[1];   // [64,2048] fp32
    float* out = (float*)d_out;
    const int wbase = (out_size - 1) / 2;     // 32768

    cudaFuncSetAttribute(k_gate, cudaFuncAttributeMaxDynamicSharedMemorySize, SMEM_BYTES);

    k_wconv<<<128, 256>>>(W);
    k_gate<<<NT / TM, THREADS, SMEM_BYTES>>>(X, out, wbase);
    k_fixup<<<296, 256>>>(X, W, out, wbase);
    k_aux<<<1, NB * NE>>>(out, out_size - 1);
}

// round 9
// speedup vs baseline: 6.1995x; 6.1995x over previous
#include <cuda_runtime.h>
#include <cuda_fp16.h>
#include <cstdint>
#include <math.h>

#define NT 16384
#define HH 2048
#define NE 64
#define NB 4
#define NS 4096
#define TM 128          // tokens per CTA
#define KT 64           // K elems per tile
#define NTILES (HH/KT)  // 32
#define THREADS 256
#define SMEM_BYTES 49408
#define TAU 2e-3f
#define MAXFIX 16384

// persistent scratch (allocation-free rule: __device__ globals)
__device__ float    g_ssum[NB * NE];
__device__ int      g_cnt[NB * NE];
__device__ uint32_t g_wh[NE * HH / 2];   // fp16x2-packed W
__device__ int      g_nfix;
__device__ int      g_fix[MAXFIX];

// ---------------- helpers ----------------
__device__ __forceinline__ uint32_t smem_u32(const void* p) {
    uint32_t a;
    asm("{ .reg .u64 t; cvta.to.shared.u64 t, %1; cvt.u32.u64 %0, t; }" : "=r"(a) : "l"(p));
    return a;
}
// pack two fp32 -> fp16x2 (lo arg -> bits[15:0], hi arg -> bits[31:16])
__device__ __forceinline__ uint32_t pack2h(float lo, float hi) {
    uint32_t r;
    asm("cvt.rn.f16x2.f32 %0, %1, %2;" : "=r"(r) : "f"(hi), "f"(lo));
    return r;
}
__device__ __forceinline__ void ldsm4(uint32_t* r, uint32_t addr) {
    asm volatile("ldmatrix.sync.aligned.m8n8.x4.shared.b16 {%0,%1,%2,%3}, [%4];"
                 : "=r"(r[0]), "=r"(r[1]), "=r"(r[2]), "=r"(r[3]) : "r"(addr));
}
__device__ __forceinline__ void mma16816(float* d, const uint32_t* a, const uint32_t* b) {
    asm volatile("mma.sync.aligned.m16n8k16.row.col.f32.f16.f16.f32 "
                 "{%0,%1,%2,%3}, {%4,%5,%6,%7}, {%8,%9}, {%0,%1,%2,%3};"
                 : "+f"(d[0]), "+f"(d[1]), "+f"(d[2]), "+f"(d[3])
                 : "r"(a[0]), "r"(a[1]), "r"(a[2]), "r"(a[3]), "r"(b[0]), "r"(b[1]));
}

// ---------------- W convert kernel (+ fixup counter reset) ----------------
__global__ __launch_bounds__(256) void k_wconv(const float* __restrict__ W) {
    if (blockIdx.x == 0 && threadIdx.x == 0) g_nfix = 0;
    int i = (blockIdx.x * 256 + threadIdx.x) * 4;
    float4 v = *(const float4*)(W + i);
    ((uint2*)g_wh)[i >> 2] = make_uint2(pack2h(v.x, v.y), pack2h(v.z, v.w));
}

// ---------------- main gate kernel (single fp16 HMMA product) ----------------
__global__ __launch_bounds__(THREADS, 1)
void k_gate(const float* __restrict__ X, float* __restrict__ out, int wbase) {
    extern __shared__ char smem[];
    const int tid  = threadIdx.x;
    const int wid  = tid >> 5;
    const int lane = tid & 31;
    const uint32_t sb = smem_u32(smem);
    const int tokBase = blockIdx.x * TM;

    int* scnt = (int*)(smem + 49152);
    if (tid < NE) scnt[tid] = 0;

    // smem: A(s) = sb + s*16384 (128 rows x 128B); B(s) = sb + 32768 + s*8192 (64 rows x 128B)
    const uint32_t HA = sb;
    const uint32_t HB = sb + 32768u;

    // ---- gmem addressing ----
    const int xr = tid >> 4;
    const float* xp = X + (size_t)(tokBase + xr) * HH + (tid & 15) * 4;
    const int wr = tid >> 3;
    const int wc = tid & 7;
    const int wbase4 = wr * 256 + wc;   // uint4 idx into g_wh rows

    // ---- STS swizzled offsets ----
    uint32_t xoff[8], woff[2];
#pragma unroll
    for (int p = 0; p < 8; p++) {
        uint32_t off = (uint32_t)(xr + 16 * p) * 128u + (uint32_t)(tid & 15) * 8u;
        xoff[p] = off ^ ((off >> 3) & 0x70);
    }
#pragma unroll
    for (int q = 0; q < 2; q++) {
        uint32_t off = (uint32_t)(wr + 32 * q) * 128u + (uint32_t)wc * 16u;
        woff[q] = off ^ ((off >> 3) & 0x70);
    }

    // ---- LDSM addressing ----
    const int wm = wid & 3;
    const int wn = wid >> 2;
    const uint32_t xorK  = (uint32_t)(lane & 7);
    const uint32_t kselA = (uint32_t)(lane >> 4);
    const uint32_t kselB = (uint32_t)((lane >> 3) & 1);
    uint32_t rowA[2], rowB[2];
#pragma unroll
    for (int mt = 0; mt < 2; mt++)
        rowA[mt] = (uint32_t)(wm * 32 + mt * 16 + (lane & 15)) * 128u;
    {
        int nB = ((lane >> 4) * 8) + (lane & 7);
#pragma unroll
        for (int pr = 0; pr < 2; pr++)
            rowB[pr] = (uint32_t)(wn * 32 + pr * 16 + nB) * 128u;
    }

    float acc[2][4][4];
#pragma unroll
    for (int mt = 0; mt < 2; mt++)
#pragma unroll
        for (int q = 0; q < 4; q++)
#pragma unroll
            for (int e = 0; e < 4; e++) acc[mt][q][e] = 0.0f;

    // ---- prologue: load tile 0 into regs ----
    float4 xv[8];
    uint4 wv[2];
#pragma unroll
    for (int p = 0; p < 8; p++) xv[p] = *(const float4*)(xp + (size_t)p * 16 * HH);
#pragma unroll
    for (int q = 0; q < 2; q++) wv[q] = ((const uint4*)g_wh)[wbase4 + q * 8192];

    for (int t = 0; t < NTILES; t++) {
        const int s = t & 1;
        const uint32_t A = HA + (uint32_t)s * 16384u;
        const uint32_t B = HB + (uint32_t)s * 8192u;

        // convert + STS current tile
#pragma unroll
        for (int p = 0; p < 8; p++) {
            uint32_t h01 = pack2h(xv[p].x, xv[p].y);
            uint32_t h23 = pack2h(xv[p].z, xv[p].w);
            asm volatile("st.shared.v2.u32 [%0], {%1,%2};" :: "r"(A + xoff[p]), "r"(h01), "r"(h23));
        }
#pragma unroll
        for (int q = 0; q < 2; q++)
            asm volatile("st.shared.v4.b32 [%0], {%1,%2,%3,%4};"
                         :: "r"(B + woff[q]), "r"(wv[q].x), "r"(wv[q].y), "r"(wv[q].z), "r"(wv[q].w));

        // prefetch next tile (overlaps sync + MMA)
        if (t + 1 < NTILES) {
            const int tn = t + 1;
#pragma unroll
            for (int p = 0; p < 8; p++)
                xv[p] = *(const float4*)(xp + tn * KT + (size_t)p * 16 * HH);
#pragma unroll
            for (int q = 0; q < 2; q++)
                wv[q] = ((const uint4*)g_wh)[wbase4 + tn * 8 + q * 8192];
        }

        __syncthreads();

        // ---- ldmatrix + mma over buf s ----
#pragma unroll
        for (int ks = 0; ks < 4; ks++) {
            const uint32_t kA = (uint32_t)(2 * ks) + kselA;
            const uint32_t kB = (uint32_t)(2 * ks) + kselB;
            uint32_t bf[8];
#pragma unroll
            for (int pr = 0; pr < 2; pr++)
                ldsm4(&bf[pr * 4], B + rowB[pr] + ((kB ^ xorK) << 4));
            uint32_t af[2][4];
            ldsm4(af[0], A + rowA[0] + ((kA ^ xorK) << 4));
            ldsm4(af[1], A + rowA[1] + ((kA ^ xorK) << 4));
#pragma unroll
            for (int mt = 0; mt < 2; mt++)
#pragma unroll
                for (int q = 0; q < 4; q++)
                    mma16816(acc[mt][q], af[mt], &bf[q * 2]);
        }
    }

    __syncthreads();   // buffers free; reuse as logits

    // ---- accumulators -> logits smem [128][66] ----
    float* Lg = (float*)smem;
    {
        const int g  = lane >> 2;
        const int tg = lane & 3;
#pragma unroll
        for (int mt = 0; mt < 2; mt++)
#pragma unroll
            for (int q = 0; q < 4; q++) {
                int m0 = wm * 32 + mt * 16 + g;
                int c  = wn * 32 + q * 8 + tg * 2;
                Lg[m0 * 66 + c]           = acc[mt][q][0];
                Lg[m0 * 66 + c + 1]       = acc[mt][q][1];
                Lg[(m0 + 8) * 66 + c]     = acc[mt][q][2];
                Lg[(m0 + 8) * 66 + c + 1] = acc[mt][q][3];
            }
    }
    __syncthreads();

    // ---- per-token softmax / top-2 (+ near-tie flagging) ----
    if (tid < TM) {
        float v[64];
#pragma unroll
        for (int e = 0; e < NE; e++) v[e] = Lg[tid * 66 + e];

        float m = -1e30f;
#pragma unroll
        for (int e = 0; e < NE; e++) m = fmaxf(m, v[e]);

        float Z = 0.0f, b1 = -1e30f, b2 = -1e30f, b3 = -1e30f;
        int i1 = 0, i2 = 0;
#pragma unroll
        for (int e = 0; e < NE; e++) {
            float x = v[e];
            float ex = __expf(x - m);
            v[e] = ex;
            Z += ex;
            if (x > b1)      { b3 = b2; b2 = b1; i2 = i1; b1 = x; i1 = e; }
            else if (x > b2) { b3 = b2; b2 = x;  i2 = e; }
            else if (x > b3) { b3 = x; }
        }
        float invZ = 1.0f / Z;
        float s1 = v[i1] * invZ;
        float s2 = v[i2] * invZ;
        float den = s1 + s2 + 1e-20f;

        int gt = tokBase + tid;
        out[gt * 2 + 0] = (float)i1;
        out[gt * 2 + 1] = (float)i2;
        out[wbase + gt * 2 + 0] = s1 / den;
        out[wbase + gt * 2 + 1] = s2 / den;

        if ((b1 - b2 < TAU) || (b2 - b3 < TAU)) {
            int slot = atomicAdd(&g_nfix, 1);
            if (slot < MAXFIX) g_fix[slot] = gt;
        }

        atomicAdd(&scnt[i1], 1);
        atomicAdd(&scnt[i2], 1);

#pragma unroll
        for (int e = 0; e < NE; e++) Lg[tid * 66 + e] = v[e] * invZ;
    }
    __syncthreads();

    if (tid < NE) {
        float ssum = 0.0f;
        for (int r = 0; r < TM; r++) ssum += Lg[r * 66 + tid];
        const int b = tokBase >> 12;
        atomicAdd(&g_ssum[b * NE + tid], ssum);
        int c = scnt[tid];
        if (c) atomicAdd(&g_cnt[b * NE + tid], c);
    }
}

// ---------------- fp32 exact fixup for near-tie tokens (coalesced) ----------------
// block = one token; warp w handles experts w*8 .. w*8+7; lane-major float4 loads.
__global__ __launch_bounds__(256) void k_fixup(const float* __restrict__ X,
                                               const float* __restrict__ W,
                                               float* __restrict__ out, int wbase) {
    __shared__ float lg[64];
    int n = g_nfix;
    if (n > MAXFIX) n = MAXFIX;
    const int tid  = threadIdx.x;
    const int w    = tid >> 5;
    const int lane = tid & 31;

    for (int s = blockIdx.x; s < n; s += gridDim.x) {
        const int gt = g_fix[s];
        const float4* xr = (const float4*)(X + (size_t)gt * HH);

#pragma unroll
        for (int q = 0; q < 8; q++) {
            const int e = w * 8 + q;
            const float4* wr = (const float4*)(W + (size_t)e * HH);
            float a0 = 0.f, a1 = 0.f;
#pragma unroll
            for (int i = 0; i < 16; i += 2) {
                float4 x0 = xr[lane + 32 * i];
                float4 w0 = wr[lane + 32 * i];
                float4 x1 = xr[lane + 32 * (i + 1)];
                float4 w1 = wr[lane + 32 * (i + 1)];
                a0 = fmaf(x0.x, w0.x, a0); a0 = fmaf(x0.y, w0.y, a0);
                a0 = fmaf(x0.z, w0.z, a0); a0 = fmaf(x0.w, w0.w, a0);
                a1 = fmaf(x1.x, w1.x, a1); a1 = fmaf(x1.y, w1.y, a1);
                a1 = fmaf(x1.z, w1.z, a1); a1 = fmaf(x1.w, w1.w, a1);
            }
            float a = a0 + a1;
#pragma unroll
            for (int off = 16; off > 0; off >>= 1)
                a += __shfl_xor_sync(0xffffffffu, a, off);
            if (lane == 0) lg[e] = a;
        }
        __syncthreads();

        if (tid == 0) {
            float m = -1e30f;
            for (int q = 0; q < 64; q++) m = fmaxf(m, lg[q]);
            float Z = 0.f, b1 = -1e30f, b2 = -1e30f;
            int i1 = 0, i2 = 0;
            for (int q = 0; q < 64; q++) {
                float x = lg[q];
                Z += __expf(x - m);
                if (x > b1)      { b2 = b1; i2 = i1; b1 = x; i1 = q; }
                else if (x > b2) { b2 = x;  i2 = q; }
            }
            float s1 = __expf(b1 - m) / Z;
            float s2 = __expf(b2 - m) / Z;
            float den = s1 + s2 + 1e-20f;

            int o1 = (int)out[gt * 2 + 0];
            int o2 = (int)out[gt * 2 + 1];
            const int b = gt >> 12;
            if (o1 != i1) { atomicAdd(&g_cnt[b * NE + o1], -1); atomicAdd(&g_cnt[b * NE + i1], 1); }
            if (o2 != i2) { atomicAdd(&g_cnt[b * NE + o2], -1); atomicAdd(&g_cnt[b * NE + i2], 1); }

            out[gt * 2 + 0] = (float)i1;
            out[gt * 2 + 1] = (float)i2;
            out[wbase + gt * 2 + 0] = s1 / den;
            out[wbase + gt * 2 + 1] = s2 / den;
        }
        __syncthreads();
    }
}

// ---------------- aux loss + scratch reset ----------------
__global__ void k_aux(float* __restrict__ out, int aux_idx) {
    __shared__ float red[NB * NE];
    int i = threadIdx.x;
    float v = (float)g_cnt[i] * ((float)NE / (float)(NS * 2)) * (g_ssum[i] / (float)NS);
    red[i] = v;
    g_cnt[i] = 0;       // reset for next graph replay
    g_ssum[i] = 0.0f;
    __syncthreads();
    for (int s = 128; s > 0; s >>= 1) {
        if (i < s) red[i] += red[i + s];
        __syncthreads();
    }
    if (i == 0) out[aux_idx] = red[0] / (float)NB * 0.1f;
}

extern "C" void kernel_launch(void* const* d_in, const int* in_sizes, int n_in,
                              void* d_out, int out_size) {
    const float* X = (const float*)d_in[0];   // [4,4096,2048] fp32
    const float* W = (const float*)d_in[1];   // [64,2048] fp32
    float* out = (float*)d_out;
    const int wbase = (out_size - 1) / 2;     // 32768

    cudaFuncSetAttribute(k_gate, cudaFuncAttributeMaxDynamicSharedMemorySize, SMEM_BYTES);

    k_wconv<<<128, 256>>>(W);
    k_gate<<<NT / TM, THREADS, SMEM_BYTES>>>(X, out, wbase);
    k_fixup<<<296, 256>>>(X, W, out, wbase);
    k_aux<<<1, NB * NE>>>(out, out_size - 1);
}